// round 3
// baseline (speedup 1.0000x reference)
#include <cuda_runtime.h>
#include <cuda_bf16.h>
#include <cstdint>

// ---------------------------------------------------------------------------
// SNN MLP forward:
//   U1 = X @ W1            (one big GEMM over all T*B rows)
//   S1 = LIF-scan(U1) over t per (b,h) chain
//   U2 = S1 @ W2           (skinny GEMM, spike-sparse)
//   S2 = LIF-scan(U2) over t per (b,o) chain
// ---------------------------------------------------------------------------

#define T_STEPS 100
#define BATCH   256
#define IN_DIM  784
#define HID_DIM 1024
#define OUT_DIM 10

#define M_ROWS  (T_STEPS * BATCH)      // 25600
#define DECAY_F 0.6f
#define THRESH_F 0.9f

// Scratch (device globals: allowed; no cudaMalloc anywhere)
__device__ float g_u1[(size_t)M_ROWS * HID_DIM];   // 104 MB
__device__ float g_u2[(size_t)M_ROWS * OUT_DIM];   // 1 MB
__device__ float g_s1[(size_t)M_ROWS * HID_DIM];   // 104 MB (used only if hidden not in d_out)

// ---------------------------------------------------------------------------
// Kernel 1: fp32 SIMT GEMM  U1[M,N] = X[M,K] @ W1[K,N]
//   M=25600, N=1024, K=784.  BM=BN=128, BK=16, 256 threads, 8x8 microtile.
// ---------------------------------------------------------------------------
#define BM 128
#define BN 128
#define BK 16
#define TM 8
#define TN 8

__global__ void __launch_bounds__(256, 2)
gemm1_kernel(const float* __restrict__ X, const float* __restrict__ W1)
{
    __shared__ __align__(16) float As[BK][BM];   // A stored transposed
    __shared__ __align__(16) float Bs[BK][BN];

    const int K = IN_DIM;
    const int N = HID_DIM;

    const int bx = blockIdx.x;            // N tile: 0..7
    const int by = blockIdx.y;            // M tile: 0..199
    const int tid = threadIdx.x;
    const int tx = tid & 15;              // 0..15 over N
    const int ty = tid >> 4;              // 0..15 over M

    const float* Ablk = X  + (size_t)by * BM * K;
    const float* Bblk = W1 + (size_t)bx * BN;

    float acc[TM][TN];
#pragma unroll
    for (int i = 0; i < TM; i++)
#pragma unroll
        for (int j = 0; j < TN; j++) acc[i][j] = 0.0f;

    for (int k0 = 0; k0 < K; k0 += BK) {
        // Load A tile (128 rows x 16 k) as 512 float4s, store transposed.
#pragma unroll
        for (int i = 0; i < 2; i++) {
            int f  = tid + i * 256;          // 0..511
            int m  = f >> 2;
            int kq = (f & 3) << 2;
            float4 v = *reinterpret_cast<const float4*>(Ablk + (size_t)m * K + k0 + kq);
            As[kq + 0][m] = v.x;
            As[kq + 1][m] = v.y;
            As[kq + 2][m] = v.z;
            As[kq + 3][m] = v.w;
        }
        // Load B tile (16 k x 128 n) as 512 float4s.
#pragma unroll
        for (int i = 0; i < 2; i++) {
            int f  = tid + i * 256;
            int kr = f >> 5;
            int nq = (f & 31) << 2;
            *reinterpret_cast<float4*>(&Bs[kr][nq]) =
                *reinterpret_cast<const float4*>(Bblk + (size_t)(k0 + kr) * N + nq);
        }
        __syncthreads();

#pragma unroll
        for (int kk = 0; kk < BK; kk++) {
            float a[TM], b[TN];
            float4 a0 = *reinterpret_cast<const float4*>(&As[kk][ty * TM]);
            float4 a1 = *reinterpret_cast<const float4*>(&As[kk][ty * TM + 4]);
            float4 b0 = *reinterpret_cast<const float4*>(&Bs[kk][tx * TN]);
            float4 b1 = *reinterpret_cast<const float4*>(&Bs[kk][tx * TN + 4]);
            a[0]=a0.x; a[1]=a0.y; a[2]=a0.z; a[3]=a0.w;
            a[4]=a1.x; a[5]=a1.y; a[6]=a1.z; a[7]=a1.w;
            b[0]=b0.x; b[1]=b0.y; b[2]=b0.z; b[3]=b0.w;
            b[4]=b1.x; b[5]=b1.y; b[6]=b1.z; b[7]=b1.w;
#pragma unroll
            for (int i = 0; i < TM; i++)
#pragma unroll
                for (int j = 0; j < TN; j++)
                    acc[i][j] = fmaf(a[i], b[j], acc[i][j]);
        }
        __syncthreads();
    }

    // Write out 128x128 tile with float4 stores.
    float* Cp = g_u1 + (size_t)(by * BM) * N + (size_t)bx * BN;
#pragma unroll
    for (int i = 0; i < TM; i++) {
        float4 v0 = make_float4(acc[i][0], acc[i][1], acc[i][2], acc[i][3]);
        float4 v1 = make_float4(acc[i][4], acc[i][5], acc[i][6], acc[i][7]);
        float* r = Cp + (size_t)(ty * TM + i) * N + tx * TN;
        *reinterpret_cast<float4*>(r)     = v0;
        *reinterpret_cast<float4*>(r + 4) = v1;
    }
}

// ---------------------------------------------------------------------------
// Kernel 2: LIF scan for hidden layer. One thread per (b,h) chain.
//   chain idx = b*H + h ; element (t,b,h) lives at t*B*H + idx.
// ---------------------------------------------------------------------------
__global__ void lif1_kernel(float* __restrict__ Sdst)
{
    const int idx = blockIdx.x * blockDim.x + threadIdx.x;
    if (idx >= BATCH * HID_DIM) return;
    const size_t stride = (size_t)BATCH * HID_DIM;

    float mem = 0.0f;
#pragma unroll 4
    for (int t = 0; t < T_STEPS; t++) {
        float u = g_u1[(size_t)t * stride + idx];
        mem = mem * DECAY_F + u;
        float s = (mem >= THRESH_F) ? 1.0f : 0.0f;
        mem -= s * THRESH_F;
        Sdst[(size_t)t * stride + idx] = s;
    }
}

// ---------------------------------------------------------------------------
// Kernel 3: U2 = S1 @ W2. One warp per row of S1; skip zero spikes (sparse).
// ---------------------------------------------------------------------------
__global__ void gemm2_kernel(const float* __restrict__ S,
                             const float* __restrict__ W2)
{
    const int gwarp = (blockIdx.x * blockDim.x + threadIdx.x) >> 5;
    const int lane  = threadIdx.x & 31;
    if (gwarp >= M_ROWS) return;

    const float* row = S + (size_t)gwarp * HID_DIM;
    float acc[OUT_DIM];
#pragma unroll
    for (int o = 0; o < OUT_DIM; o++) acc[o] = 0.0f;

    for (int k = lane; k < HID_DIM; k += 32) {
        float s = row[k];
        if (s != 0.0f) {                      // spikes are exactly 0.0 or 1.0
            const float* w = W2 + (size_t)k * OUT_DIM;
#pragma unroll
            for (int o = 0; o < OUT_DIM; o++) acc[o] += w[o];
        }
    }
#pragma unroll
    for (int o = 0; o < OUT_DIM; o++) {
#pragma unroll
        for (int off = 16; off > 0; off >>= 1)
            acc[o] += __shfl_xor_sync(0xFFFFFFFFu, acc[o], off);
    }
    if (lane == 0) {
#pragma unroll
        for (int o = 0; o < OUT_DIM; o++)
            g_u2[(size_t)gwarp * OUT_DIM + o] = acc[o];
    }
}

// ---------------------------------------------------------------------------
// Kernel 4: LIF scan for output layer. One thread per (b,o) chain (2560).
// ---------------------------------------------------------------------------
__global__ void lif2_kernel(float* __restrict__ Odst)
{
    const int idx = blockIdx.x * blockDim.x + threadIdx.x;
    if (idx >= BATCH * OUT_DIM) return;
    const size_t stride = (size_t)BATCH * OUT_DIM;

    float mem = 0.0f;
#pragma unroll 4
    for (int t = 0; t < T_STEPS; t++) {
        float u = g_u2[(size_t)t * stride + idx];
        mem = mem * DECAY_F + u;
        float s = (mem >= THRESH_F) ? 1.0f : 0.0f;
        mem -= s * THRESH_F;
        Odst[(size_t)t * stride + idx] = s;
    }
}

// ---------------------------------------------------------------------------
// Launch
// ---------------------------------------------------------------------------
extern "C" void kernel_launch(void* const* d_in, const int* in_sizes, int n_in,
                              void* d_out, int out_size)
{
    const float* X  = (const float*)d_in[0];   // [T,B,I]
    const float* W1 = (const float*)d_in[1];   // [I,H]
    const float* W2 = (const float*)d_in[2];   // [H,O]
    float* out = (float*)d_out;

    const long long TBH = (long long)T_STEPS * BATCH * HID_DIM;   // 26,214,400
    const long long TBO = (long long)T_STEPS * BATCH * OUT_DIM;   //    256,000

    float* hid_dst;
    float* out_dst;
    if ((long long)out_size == TBH + TBO) {
        // (hidden_all, output_all) concatenated — expected case
        hid_dst = out;
        out_dst = out + TBH;
    } else if ((long long)out_size == TBO) {
        // only output spikes compared; stash hidden spikes in scratch
        void* p = nullptr;
        cudaGetSymbolAddress(&p, g_s1);
        hid_dst = (float*)p;
        out_dst = out;
    } else {
        // only hidden spikes (or unknown) — hidden into d_out, output into scratch tail
        hid_dst = out;
        void* p = nullptr;
        cudaGetSymbolAddress(&p, g_s1);
        out_dst = (float*)p;
    }

    // 1) U1 = X @ W1
    {
        dim3 grid(HID_DIM / BN, M_ROWS / BM);   // (8, 200)
        gemm1_kernel<<<grid, 256>>>(X, W1);
    }
    // 2) hidden LIF scan -> spikes
    {
        int n = BATCH * HID_DIM;                 // 262144
        lif1_kernel<<<(n + 255) / 256, 256>>>(hid_dst);
    }
    // 3) U2 = S1 @ W2 (warp per row)
    {
        int warps = M_ROWS;                      // 25600
        int threads = 256;
        int blocks = (warps * 32 + threads - 1) / threads;   // 3200
        gemm2_kernel<<<blocks, threads>>>(hid_dst, W2);
    }
    // 4) output LIF scan
    {
        int n = BATCH * OUT_DIM;                 // 2560
        lif2_kernel<<<(n + 255) / 256, 256>>>(out_dst);
    }
}

// round 4
// speedup vs baseline: 3.0432x; 3.0432x over previous
#include <cuda_runtime.h>
#include <cuda_bf16.h>
#include <cstdint>

// ---------------------------------------------------------------------------
// SNN MLP forward, tensor-core edition:
//   Xb    = bf16(X)            (X is binary {0,1} -> exact in bf16)
//   W1    = W1hi + W1lo        (bf16 split -> ~fp32-accurate product)
//   U1    = Xb @ W1hi + Xb @ W1lo   (mma.sync bf16, fp32 accum)
//   S1    = LIF-scan(U1)
//   U2    = S1 @ W2            (warp-per-row, spike-sparse, fp32)
//   S2    = LIF-scan(U2)
// ---------------------------------------------------------------------------

#define T_STEPS  100
#define BATCH    256
#define IN_DIM   784
#define HID_DIM  1024
#define OUT_DIM  10
#define M_ROWS   (T_STEPS * BATCH)     // 25600
#define KP       800                   // K padded to multiple of 32
#define DECAY_F  0.6f
#define THRESH_F 0.9f

// GEMM tiling
#define BMg 128
#define BNg 128
#define BKg 32
#define AS_STRIDE 40    // 32 + 8 pad (bf16 units; 80B rows, 16B-aligned)
#define BS_STRIDE 136   // 128 + 8 pad (272B rows, 16B-aligned)
#define AS_BUF (BMg * AS_STRIDE)   // 5120 bf16
#define BS_BUF (BKg * BS_STRIDE)   // 4352 bf16
#define SMEM_BF16 (2*AS_BUF + 4*BS_BUF)          // 27648 bf16
#define SMEM_BYTES (SMEM_BF16 * 2)               // 55296 B

// Device scratch (no cudaMalloc anywhere)
__device__ float g_u1[(size_t)M_ROWS * HID_DIM];   // 104 MB
__device__ float g_u2[(size_t)M_ROWS * OUT_DIM];   //   1 MB
__device__ float g_s1[(size_t)M_ROWS * HID_DIM];   // fallback hidden store
__device__ __align__(16) __nv_bfloat16 g_xb[(size_t)M_ROWS * KP];     // 41 MB
__device__ __align__(16) __nv_bfloat16 g_w1hi[(size_t)KP * HID_DIM];  // 1.6 MB
__device__ __align__(16) __nv_bfloat16 g_w1lo[(size_t)KP * HID_DIM];  // 1.6 MB

// ---------------------------------------------------------------------------
// PTX helpers
// ---------------------------------------------------------------------------
__device__ __forceinline__ void cp_async16(uint32_t dst, const void* src) {
    asm volatile("cp.async.cg.shared.global [%0], [%1], 16;\n" :: "r"(dst), "l"(src));
}
__device__ __forceinline__ void cp_commit() {
    asm volatile("cp.async.commit_group;\n" ::: "memory");
}
__device__ __forceinline__ void cp_wait1() {
    asm volatile("cp.async.wait_group 1;\n" ::: "memory");
}
__device__ __forceinline__ void ldsm_x4(uint32_t* r, uint32_t addr) {
    asm volatile("ldmatrix.sync.aligned.m8n8.x4.shared.b16 {%0,%1,%2,%3}, [%4];"
                 : "=r"(r[0]), "=r"(r[1]), "=r"(r[2]), "=r"(r[3]) : "r"(addr));
}
__device__ __forceinline__ void ldsm_x4_t(uint32_t* r, uint32_t addr) {
    asm volatile("ldmatrix.sync.aligned.m8n8.x4.trans.shared.b16 {%0,%1,%2,%3}, [%4];"
                 : "=r"(r[0]), "=r"(r[1]), "=r"(r[2]), "=r"(r[3]) : "r"(addr));
}
__device__ __forceinline__ void mma_bf16(float* c, const uint32_t* a,
                                         uint32_t b0, uint32_t b1) {
    asm volatile(
        "mma.sync.aligned.m16n8k16.row.col.f32.bf16.bf16.f32 "
        "{%0,%1,%2,%3}, {%4,%5,%6,%7}, {%8,%9}, {%0,%1,%2,%3};"
        : "+f"(c[0]), "+f"(c[1]), "+f"(c[2]), "+f"(c[3])
        : "r"(a[0]), "r"(a[1]), "r"(a[2]), "r"(a[3]), "r"(b0), "r"(b1));
}

// ---------------------------------------------------------------------------
// Conversion: X fp32 [25600,784] -> g_xb bf16 [25600,800] (zero-padded tail)
// One thread per 8 output elems.
// ---------------------------------------------------------------------------
__global__ void conv_x_kernel(const float* __restrict__ X)
{
    int idx = blockIdx.x * blockDim.x + threadIdx.x;
    const int chunks = KP / 8;                       // 100
    if (idx >= M_ROWS * chunks) return;
    int c = idx % chunks;
    int r = idx / chunks;

    __align__(16) __nv_bfloat162 o[4];
    if (c < IN_DIM / 8) {
        const float4* p = reinterpret_cast<const float4*>(X + (size_t)r * IN_DIM + c * 8);
        float4 a = p[0];
        float4 b = p[1];
        o[0] = __float22bfloat162_rn(make_float2(a.x, a.y));
        o[1] = __float22bfloat162_rn(make_float2(a.z, a.w));
        o[2] = __float22bfloat162_rn(make_float2(b.x, b.y));
        o[3] = __float22bfloat162_rn(make_float2(b.z, b.w));
    } else {
        o[0] = o[1] = o[2] = o[3] = __float22bfloat162_rn(make_float2(0.f, 0.f));
    }
    *reinterpret_cast<uint4*>(&g_xb[(size_t)r * KP + c * 8]) =
        *reinterpret_cast<const uint4*>(o);
}

// ---------------------------------------------------------------------------
// Conversion: W1 fp32 [784,1024] -> hi/lo bf16 [800,1024] (zero pad rows)
// One thread per 4 elems.
// ---------------------------------------------------------------------------
__global__ void conv_w_kernel(const float* __restrict__ W1)
{
    int idx = blockIdx.x * blockDim.x + threadIdx.x;
    const int rowq = HID_DIM / 4;                    // 256
    if (idx >= KP * rowq) return;
    int c = idx % rowq;
    int r = idx / rowq;

    __align__(8) __nv_bfloat16 hi[4], lo[4];
    if (r < IN_DIM) {
        float4 w = *reinterpret_cast<const float4*>(W1 + (size_t)r * HID_DIM + c * 4);
        float wv[4] = {w.x, w.y, w.z, w.w};
#pragma unroll
        for (int i = 0; i < 4; i++) {
            hi[i] = __float2bfloat16_rn(wv[i]);
            lo[i] = __float2bfloat16_rn(wv[i] - __bfloat162float(hi[i]));
        }
    } else {
#pragma unroll
        for (int i = 0; i < 4; i++) { hi[i] = __float2bfloat16_rn(0.f); lo[i] = hi[i]; }
    }
    *reinterpret_cast<uint2*>(&g_w1hi[(size_t)r * HID_DIM + c * 4]) =
        *reinterpret_cast<const uint2*>(hi);
    *reinterpret_cast<uint2*>(&g_w1lo[(size_t)r * HID_DIM + c * 4]) =
        *reinterpret_cast<const uint2*>(lo);
}

// ---------------------------------------------------------------------------
// GEMM1 (tensor cores): U1[M,N] = Xb @ (W1hi + W1lo), fp32 accum.
// BM=BN=128, BK=32, 256 thr (8 warps as 2(M)x4(N), warp tile 64x32),
// double-buffered cp.async.
// ---------------------------------------------------------------------------
__global__ void __launch_bounds__(256, 2)
gemm1_tc_kernel()
{
    extern __shared__ __nv_bfloat16 smem[];
    __nv_bfloat16* As = smem;                       // 2 * 5120
    __nv_bfloat16* Bh = smem + 2 * AS_BUF;          // 2 * 4352
    __nv_bfloat16* Bl = Bh + 2 * BS_BUF;            // 2 * 4352

    const int tid  = threadIdx.x;
    const int lane = tid & 31;
    const int wid  = tid >> 5;
    const int bx = blockIdx.x;        // N tile 0..7
    const int by = blockIdx.y;        // M tile 0..199
    const int wm = (wid & 1) * 64;
    const int wn = (wid >> 1) * 32;

    const __nv_bfloat16* Xg  = g_xb   + (size_t)by * BMg * KP;
    const __nv_bfloat16* Whg = g_w1hi + bx * BNg;
    const __nv_bfloat16* Wlg = g_w1lo + bx * BNg;

    const uint32_t s_as = (uint32_t)__cvta_generic_to_shared(As);
    const uint32_t s_bh = (uint32_t)__cvta_generic_to_shared(Bh);
    const uint32_t s_bl = (uint32_t)__cvta_generic_to_shared(Bl);

    float acc[4][4][4];
#pragma unroll
    for (int i = 0; i < 4; i++)
#pragma unroll
        for (int j = 0; j < 4; j++)
#pragma unroll
            for (int k = 0; k < 4; k++) acc[i][j][k] = 0.0f;

    // per-thread load coordinates
    const int am = tid >> 2, ak = (tid & 3) * 8;          // + c*256: m += 64
    const int bk = tid >> 4, bn = (tid & 15) * 8;         // + c*256: k += 16

    const int NITER = KP / BKg;                           // 25

    // ldmatrix per-lane base offsets (bf16 units)
    const int a_lane = (lane & 15) * AS_STRIDE + (lane >> 4) * 8;
    const int b_lane = (lane & 15) * BS_STRIDE + (lane >> 4) * 8;

    auto load_stage = [&](int it, int buf) {
#pragma unroll
        for (int h = 0; h < 2; h++) {
            int m = am + h * 64;
            cp_async16(s_as + (uint32_t)(buf * AS_BUF + m * AS_STRIDE + ak) * 2,
                       Xg + (size_t)m * KP + it * BKg + ak);
        }
#pragma unroll
        for (int h = 0; h < 2; h++) {
            int k = bk + h * 16;
            const size_t so = (size_t)(it * BKg + k) * HID_DIM + bn;
            uint32_t doff = (uint32_t)(buf * BS_BUF + k * BS_STRIDE + bn) * 2;
            cp_async16(s_bh + doff, Whg + so);
            cp_async16(s_bl + doff, Wlg + so);
        }
    };

    load_stage(0, 0);
    cp_commit();

    int buf = 0;
    for (int it = 0; it < NITER; it++) {
        if (it + 1 < NITER) load_stage(it + 1, buf ^ 1);
        cp_commit();
        cp_wait1();
        __syncthreads();

#pragma unroll
        for (int ks = 0; ks < 2; ks++) {
            uint32_t af[4][4];
#pragma unroll
            for (int i = 0; i < 4; i++)
                ldsm_x4(af[i], s_as + (uint32_t)(buf * AS_BUF + (wm + i * 16) * AS_STRIDE
                                                 + ks * 16 + a_lane) * 2);
            uint32_t bhf[2][4], blf[2][4];
#pragma unroll
            for (int j = 0; j < 2; j++) {
                uint32_t off = (uint32_t)(buf * BS_BUF + ks * 16 * BS_STRIDE
                                          + wn + j * 16 + b_lane) * 2;
                ldsm_x4_t(bhf[j], s_bh + off);
                ldsm_x4_t(blf[j], s_bl + off);
            }
#pragma unroll
            for (int i = 0; i < 4; i++) {
#pragma unroll
                for (int j = 0; j < 2; j++) {
                    mma_bf16(acc[i][j * 2],     af[i], bhf[j][0], bhf[j][1]);
                    mma_bf16(acc[i][j * 2 + 1], af[i], bhf[j][2], bhf[j][3]);
                    mma_bf16(acc[i][j * 2],     af[i], blf[j][0], blf[j][1]);
                    mma_bf16(acc[i][j * 2 + 1], af[i], blf[j][2], blf[j][3]);
                }
            }
        }
        __syncthreads();
        buf ^= 1;
    }

    // Epilogue: c-fragment -> g_u1 (float2 stores)
    const int rbase = by * BMg + wm + (lane >> 2);
    const int cbase = bx * BNg + wn + (lane & 3) * 2;
#pragma unroll
    for (int i = 0; i < 4; i++) {
#pragma unroll
        for (int j = 0; j < 4; j++) {
            float* p = g_u1 + (size_t)(rbase + i * 16) * HID_DIM + cbase + j * 8;
            *reinterpret_cast<float2*>(p) = make_float2(acc[i][j][0], acc[i][j][1]);
            *reinterpret_cast<float2*>(p + 8 * HID_DIM) =
                make_float2(acc[i][j][2], acc[i][j][3]);
        }
    }
}

// ---------------------------------------------------------------------------
// LIF scans (unchanged math; loads are mem-independent so they pipeline)
// ---------------------------------------------------------------------------
__global__ void lif1_kernel(float* __restrict__ Sdst)
{
    const int idx = blockIdx.x * blockDim.x + threadIdx.x;
    if (idx >= BATCH * HID_DIM) return;
    const size_t stride = (size_t)BATCH * HID_DIM;
    float mem = 0.0f;
#pragma unroll 10
    for (int t = 0; t < T_STEPS; t++) {
        float u = g_u1[(size_t)t * stride + idx];
        mem = mem * DECAY_F + u;
        float s = (mem >= THRESH_F) ? 1.0f : 0.0f;
        mem -= s * THRESH_F;
        Sdst[(size_t)t * stride + idx] = s;
    }
}

__global__ void gemm2_kernel(const float* __restrict__ S,
                             const float* __restrict__ W2)
{
    const int gwarp = (blockIdx.x * blockDim.x + threadIdx.x) >> 5;
    const int lane  = threadIdx.x & 31;
    if (gwarp >= M_ROWS) return;

    const float* row = S + (size_t)gwarp * HID_DIM;
    float acc[OUT_DIM];
#pragma unroll
    for (int o = 0; o < OUT_DIM; o++) acc[o] = 0.0f;

    for (int k = lane; k < HID_DIM; k += 32) {
        float s = row[k];
        if (s != 0.0f) {
            const float* w = W2 + (size_t)k * OUT_DIM;
#pragma unroll
            for (int o = 0; o < OUT_DIM; o++) acc[o] += w[o];
        }
    }
#pragma unroll
    for (int o = 0; o < OUT_DIM; o++) {
#pragma unroll
        for (int off = 16; off > 0; off >>= 1)
            acc[o] += __shfl_xor_sync(0xFFFFFFFFu, acc[o], off);
    }
    if (lane == 0) {
#pragma unroll
        for (int o = 0; o < OUT_DIM; o++)
            g_u2[(size_t)gwarp * OUT_DIM + o] = acc[o];
    }
}

__global__ void lif2_kernel(float* __restrict__ Odst)
{
    const int idx = blockIdx.x * blockDim.x + threadIdx.x;
    if (idx >= BATCH * OUT_DIM) return;
    const size_t stride = (size_t)BATCH * OUT_DIM;
    float mem = 0.0f;
#pragma unroll 10
    for (int t = 0; t < T_STEPS; t++) {
        float u = g_u2[(size_t)t * stride + idx];
        mem = mem * DECAY_F + u;
        float s = (mem >= THRESH_F) ? 1.0f : 0.0f;
        mem -= s * THRESH_F;
        Odst[(size_t)t * stride + idx] = s;
    }
}

// ---------------------------------------------------------------------------
// Launch
// ---------------------------------------------------------------------------
extern "C" void kernel_launch(void* const* d_in, const int* in_sizes, int n_in,
                              void* d_out, int out_size)
{
    const float* X  = (const float*)d_in[0];
    const float* W1 = (const float*)d_in[1];
    const float* W2 = (const float*)d_in[2];
    float* out = (float*)d_out;

    const long long TBH = (long long)T_STEPS * BATCH * HID_DIM;
    const long long TBO = (long long)T_STEPS * BATCH * OUT_DIM;

    float* hid_dst;
    float* out_dst;
    if ((long long)out_size == TBH + TBO) {
        hid_dst = out;
        out_dst = out + TBH;
    } else if ((long long)out_size == TBO) {
        void* p = nullptr; cudaGetSymbolAddress(&p, g_s1);
        hid_dst = (float*)p;
        out_dst = out;
    } else {
        hid_dst = out;
        void* p = nullptr; cudaGetSymbolAddress(&p, g_s1);
        out_dst = (float*)p;
    }

    // allow >48KB dynamic smem (idempotent, not an allocation)
    cudaFuncSetAttribute(gemm1_tc_kernel,
                         cudaFuncAttributeMaxDynamicSharedMemorySize, SMEM_BYTES);

    // 0) conversions
    {
        int n = M_ROWS * (KP / 8);                           // 2,560,000
        conv_x_kernel<<<(n + 255) / 256, 256>>>(X);
        int m = KP * (HID_DIM / 4);                          // 204,800
        conv_w_kernel<<<(m + 255) / 256, 256>>>(W1);
    }
    // 1) U1 = Xb @ (W1hi + W1lo)
    {
        dim3 grid(HID_DIM / BNg, M_ROWS / BMg);              // (8, 200)
        gemm1_tc_kernel<<<grid, 256, SMEM_BYTES>>>();
    }
    // 2) hidden LIF scan
    {
        int n = BATCH * HID_DIM;
        lif1_kernel<<<(n + 255) / 256, 256>>>(hid_dst);
    }
    // 3) U2 = S1 @ W2
    {
        int blocks = (M_ROWS * 32 + 255) / 256;              // 3200
        gemm2_kernel<<<blocks, 256>>>(hid_dst, W2);
    }
    // 4) output LIF scan
    {
        int n = BATCH * OUT_DIM;
        lif2_kernel<<<(n + 255) / 256, 256>>>(out_dst);
    }
}